// round 12
// baseline (speedup 1.0000x reference)
#include <cuda_runtime.h>
#include <cuda_fp16.h>
#include <cstdint>

#define FULLM 0xFFFFFFFFu
#define LOG2E 1.4426950408889634f
#define LN2F  0.6931471805599453f
#define CC 37
#define BLANKC 36
#define K1_WARPS 8
#define K2_WARPS 4
#define TILE 32
#define PW1 1496        // floats per warp of kernel-1 smem (16B-aligned stride)

// Static device scratch (no allocation allowed)
__device__ __half   g_P[2048u * 256u * 18u];   // [B][T][L+2] fp16 probs
__device__ float    g_loss[8192];
__device__ unsigned g_ctr = 0;

__device__ __forceinline__ float ex2f_(float x){float y;asm("ex2.approx.f32 %0,%1;":"=f"(y):"f"(x));return y;}
__device__ __forceinline__ float lg2f_(float x){float y;asm("lg2.approx.f32 %0,%1;":"=f"(y):"f"(x));return y;}
__device__ __forceinline__ float rcpf_(float x){float y;asm("rcp.approx.f32 %0,%1;":"=f"(y):"f"(x));return y;}

extern __shared__ float smem_dyn[];

// ============================ Kernel 1 =====================================
// One warp per 32 timesteps of one sample: coalesced stage of logits, softmax
// per row (lane = row), gather the L labels + blank + a zero slot, write fp16
// probs to g_P. Massively parallel (B*T/32 warps) and memory-bound.
__global__ void __launch_bounds__(K1_WARPS * 32)
prob_kernel(const float* __restrict__ logits, const int* __restrict__ targets,
            int B, int T, int L)
{
    const int warp = threadIdx.x >> 5, lane = threadIdx.x & 31;
    const int tilesPerB = (T + TILE - 1) / TILE;
    const int g = blockIdx.x * K1_WARPS + warp;
    if (g >= B * tilesPerB) return;
    const int b  = g / tilesPerB;
    const int t0 = (g - b * tilesPerB) * TILE;
    const int rows = min(TILE, T - t0);
    const int SLOTS = L + 2;

    float*  tileF = smem_dyn + warp * PW1;          // [32][37] scaled logits
    __half* outH  = (__half*)(tileF + 1184);        // [32][SLOTS] fp16 probs
    int*    tg    = (int*)(tileF + 1472);           // [L]

    for (int l = lane; l < L; l += 32) tg[l] = targets[b * L + l];
    __syncwarp();

    // coalesced stage, pre-scaled to log2 domain
    const float* src = logits + ((size_t)b * T + t0) * CC;
    const int nf = rows * CC;
    if (nf == TILE * CC) {
        #pragma unroll 4
        for (int j = lane; j < TILE * CC / 4; j += 32) {
            float4 v = __ldg((const float4*)src + j);
            v.x *= LOG2E; v.y *= LOG2E; v.z *= LOG2E; v.w *= LOG2E;
            ((float4*)tileF)[j] = v;
        }
    } else {
        for (int j = lane; j < nf; j += 32) tileF[j] = __ldg(src + j) * LOG2E;
    }
    __syncwarp();

    if (lane < rows) {
        const float* xr = tileF + lane * CC;        // stride 37: conflict-free
        float m0 = xr[0], m1 = xr[1];
        #pragma unroll
        for (int c = 2; c + 1 < CC; c += 2) { m0 = fmaxf(m0, xr[c]); m1 = fmaxf(m1, xr[c+1]); }
        const float m = fmaxf(fmaxf(m0, m1), xr[CC-1]);
        float s0 = 0.f, s1 = 0.f;
        #pragma unroll
        for (int c = 0; c + 1 < CC; c += 2) { s0 += ex2f_(xr[c] - m); s1 += ex2f_(xr[c+1] - m); }
        s0 += ex2f_(xr[CC-1] - m);
        const float rinv = rcpf_(s0 + s1);
        __half* pr = outH + lane * SLOTS;
        pr[L]     = __float2half_rn(ex2f_(xr[BLANKC] - m) * rinv);
        pr[L + 1] = __float2half_rn(0.f);           // zero slot for invalid states
        if (L == 16) {
            #pragma unroll
            for (int l = 0; l < 16; l++)
                pr[l] = __float2half_rn(ex2f_(xr[tg[l]] - m) * rinv);
        } else {
            for (int l = 0; l < L; l++)
                pr[l] = __float2half_rn(ex2f_(xr[tg[l]] - m) * rinv);
        }
    }
    __syncwarp();

    // coalesced fp16 store
    __half* dst = g_P + ((size_t)b * T + t0) * SLOTS;
    const int nh = rows * SLOTS;
    if ((nh & 7) == 0) {
        for (int j = lane; j < nh / 8; j += 32)
            ((uint4*)dst)[j] = ((const uint4*)outH)[j];
    } else {
        for (int j = lane; j < nh; j += 32) dst[j] = outH[j];
    }
}

// ============================ Kernel 2 =====================================
// One warp per sample; pure linear-domain recursion. Lane k owns state k+1;
// state 0 replicated. Per-tile: coalesced fp16->fp32 stage into smem, then 32
// steps of register/shuffle math (no MUFU in the loop); exact power-of-2
// renorm every 4 steps. Fused deterministic mean via last-block ticket.
__global__ void __launch_bounds__(K2_WARPS * 32)
rec_kernel(const int* __restrict__ targets, const int* __restrict__ in_len,
           const int* __restrict__ tgt_len, float* __restrict__ out,
           int B, int T, int L, int nBlocks)
{
    const int warp = threadIdx.x >> 5, lane = threadIdx.x & 31;
    const int b = blockIdx.x * K2_WARPS + warp;
    const int SLOTS = L + 2;
    float* Pt = smem_dyn + warp * TILE * SLOTS;     // [32][SLOTS] fp32 probs

    if (b < B) {
        const int tl   = tgt_len[b];
        const int il   = in_len[b];
        const int endi = 2 * tl;
        const int  s    = lane + 1;
        const bool sOdd = (s & 1);
        const int  li   = (s - 1) >> 1;
        const bool vS   = (s < endi + 1);
        bool canSkip = false;
        if (sOdd && s >= 3 && li < L)
            canSkip = (__ldg(targets + b*L + li) != __ldg(targets + b*L + li - 1));
        const int myIdx = !vS ? (L + 1) : (sOdd ? li : L);   // zero slot if invalid

        float alpha = 0.f, a0 = 0.f, acc2 = 0.f, fin = -1e30f;
        int t = 0;

#define CTC_CAPTURE() do {                                                    \
            float e1 = (endi == 0) ? a0 : __shfl_sync(FULLM, alpha, endi-1);  \
            float e2 = (endi == 1) ? a0 :                                     \
                       ((endi >= 2) ? __shfl_sync(FULLM, alpha, endi-2) : 0.f);\
            fin = lg2f_(e1 + e2) + acc2;                                      \
        } while (0)

        for (int t0 = 0; t0 < T; t0 += TILE) {
            const int rows = min(TILE, T - t0);
            // stage fp16 -> fp32 (g_P is L2-resident; coalesced uint4)
            const __half* src = g_P + ((size_t)b * T + t0) * SLOTS;
            const int nh = rows * SLOTS;
            if ((nh & 7) == 0) {
                for (int j = lane; j < nh / 8; j += 32) {
                    uint4 v = __ldg((const uint4*)src + j);
                    const __half2* hp = (const __half2*)&v;
                    float2 f0 = __half22float2(hp[0]), f1 = __half22float2(hp[1]);
                    float2 f2 = __half22float2(hp[2]), f3 = __half22float2(hp[3]);
                    float4* o = (float4*)Pt + j * 2;
                    o[0] = make_float4(f0.x, f0.y, f1.x, f1.y);
                    o[1] = make_float4(f2.x, f2.y, f3.x, f3.y);
                }
            } else {
                for (int j = lane; j < nh; j += 32) Pt[j] = __half2float(src[j]);
            }
            __syncwarp();

            int tt = 0;
            if (t0 == 0) {
                a0 = Pt[L];
                alpha = (lane == 0 && vS) ? Pt[0] : 0.f;
                acc2 = 0.f;
                if (il == 1) CTC_CAPTURE();
                tt = 1; t = 1;
            }
            const float* pr = Pt + tt * SLOTS;
            #pragma unroll 4
            for (; tt < rows; tt++, t++, pr += SLOTS) {
                const float pm = pr[myIdx];          // conflict-free: 18-word row
                const float pb = pr[L];
                float a1 = __shfl_up_sync(FULLM, alpha, 1);
                if (lane == 0) a1 = a0;
                float a2 = __shfl_up_sync(FULLM, alpha, 2);
                a2 = canSkip ? a2 : 0.f;
                alpha = (alpha + a1 + a2) * pm;
                a0 *= pb;
                if ((t & 3) == 0) {
                    // exact power-of-2 renorm; values >= 0 -> float bits monotone
                    unsigned Mi = __reduce_max_sync(FULLM,
                        (unsigned)__float_as_uint(fmaxf(alpha, a0)));
                    int e = (int)(Mi >> 23) - 127;
                    float scale = __uint_as_float((unsigned)(127 - e) << 23);
                    alpha *= scale; a0 *= scale; acc2 += (float)e;
                }
                if (t + 1 == il) CTC_CAPTURE();
            }
            __syncwarp();
            if (t >= il) break;                      // everything after il is dead
        }
#undef CTC_CAPTURE

        if (lane == 0) {
            const float tlf = (float)(tl > 0 ? tl : 1);
            g_loss[b] = -(fin * LN2F) / tlf;
        }
    }

    // ---- fused deterministic mean via last-block ticket ----
    __shared__ unsigned tkt;
    __syncthreads();
    if (threadIdx.x == 0) {
        __threadfence();
        tkt = atomicAdd(&g_ctr, 1u);
    }
    __syncthreads();
    if (tkt == (unsigned)(nBlocks - 1)) {
        __threadfence();
        float sacc = 0.f;
        for (int i = threadIdx.x; i < B; i += K2_WARPS * 32) sacc += g_loss[i];
        __shared__ float sh[K2_WARPS * 32];
        sh[threadIdx.x] = sacc;
        __syncthreads();
        if (threadIdx.x < 64) sh[threadIdx.x] += sh[threadIdx.x + 64];
        __syncthreads();
        if (threadIdx.x < 32) {
            float v = sh[threadIdx.x] + sh[threadIdx.x + 32];
            #pragma unroll
            for (int o = 16; o; o >>= 1) v += __shfl_down_sync(FULLM, v, o);
            if (threadIdx.x == 0) {
                out[0] = v / (float)B;
                g_ctr = 0;                            // graph replays identical
            }
        }
    }
}

extern "C" void kernel_launch(void* const* d_in, const int* in_sizes, int n_in,
                              void* d_out, int out_size)
{
    const float* logits  = (const float*)d_in[0];
    const int*   targets = (const int*)d_in[1];
    const int*   in_len  = (const int*)d_in[2];
    const int*   tgt_len = (const int*)d_in[3];

    const int B = in_sizes[2];
    const int L = in_sizes[1] / B;
    const int T = in_sizes[0] / (B * CC);
    const int SLOTS = L + 2;

    // kernel 1: one warp per 32-row tile
    const int tilesPerB = (T + TILE - 1) / TILE;
    const int nTiles = B * tilesPerB;
    const int blocks1 = (nTiles + K1_WARPS - 1) / K1_WARPS;
    const size_t smem1 = (size_t)K1_WARPS * PW1 * sizeof(float);   // 47.9 KB
    prob_kernel<<<blocks1, K1_WARPS * 32, smem1>>>(logits, targets, B, T, L);

    // kernel 2: one warp per sample (+ fused mean)
    const int blocks2 = (B + K2_WARPS - 1) / K2_WARPS;
    const size_t smem2 = (size_t)K2_WARPS * TILE * SLOTS * sizeof(float);
    rec_kernel<<<blocks2, K2_WARPS * 32, smem2>>>(
        targets, in_len, tgt_len, (float*)d_out, B, T, L, blocks2);
}

// round 13
// speedup vs baseline: 1.4774x; 1.4774x over previous
#include <cuda_runtime.h>
#include <cstdint>

#define FULLM 0xFFFFFFFFu
#define LOG2E 1.4426950408889634f
#define LN2F  0.6931471805599453f
#define CC 37
#define WPB 2
#define PW 2992     // floats per warp: buf0(1184) buf1(1184) P(32*19=608) tg(16)

// Static device scratch (no allocation allowed)
__device__ float    g_part[4096];
__device__ unsigned g_ctr = 0;

__device__ __forceinline__ float ex2f_(float x){float y;asm("ex2.approx.f32 %0,%1;":"=f"(y):"f"(x));return y;}
__device__ __forceinline__ float lg2f_(float x){float y;asm("lg2.approx.f32 %0,%1;":"=f"(y):"f"(x));return y;}
__device__ __forceinline__ uint32_t s2u(const void* p){return (uint32_t)__cvta_generic_to_shared(p);}
__device__ __forceinline__ void cpa16(uint32_t d,const void* s){asm volatile("cp.async.cg.shared.global [%0],[%1],16;"::"r"(d),"l"(s));}
__device__ __forceinline__ void cpa4 (uint32_t d,const void* s){asm volatile("cp.async.ca.shared.global [%0],[%1],4;"::"r"(d),"l"(s));}
__device__ __forceinline__ void cpcommit(){asm volatile("cp.async.commit_group;" ::: "memory");}

extern __shared__ float smem_dyn[];

// Fused CTC: one warp per sample. Lane k owns state k+1; state 0 replicated.
// Double-buffered cp.async logits staging; per-row ex2 (UNNORMALIZED probs,
// log2-normalizer summed separately); recursion fused 2 steps/iteration in
// linear domain (zero MUFU in the loop); exact power-of-2 renorm every 8 rows.
__global__ void __launch_bounds__(WPB*32)
ctc_kernel(const float* __restrict__ logits, const int* __restrict__ targets,
           const int* __restrict__ in_len, const int* __restrict__ tgt_len,
           float* __restrict__ out, int B, int T, int L, int nBlocks)
{
    const int warp = threadIdx.x >> 5, lane = threadIdx.x & 31;
    const int b = blockIdx.x * WPB + warp;
    float* base = smem_dyn + warp * PW;
    float* P    = base + 2368;                 // [32][19]: 0-15 labels,16 blank,17 zero,18 log2Z
    int*   tg   = (int*)(base + 2976);
    __shared__ float    blkLoss[WPB];
    __shared__ unsigned tkt;
    if (lane == 0) blkLoss[warp] = 0.f;

    if (b < B) {
        for (int l = lane; l < L; l += 32) tg[l] = targets[b*L + l];
        __syncwarp();

        const int tl = tgt_len[b], il = in_len[b];
        const int endi = 2 * tl;
        const bool sOdd = !(lane & 1);          // s = lane+1
        const int  li   = lane >> 1;
        const bool vS   = lane < endi;          // s < S = endi+1
        const bool kO  = (li >= 1) && (tg[li]   != tg[li-1]);
        const bool k2O = (li >= 2) && (tg[li-1] != tg[li-2]);
        const float fa = (sOdd && kO)  ? 1.f : 0.f;   // skip into s   (odd only)
        const float fb = (!sOdd && kO) ? 1.f : 0.f;   // skip into s-1 (even only)
        const float fc = (sOdd && k2O) ? 1.f : 0.f;   // skip into s-2 (odd only)
        const int idxA = !vS ? 17 : (sOdd ? li : 16);
        const int idxB = !vS ? 17 : (sOdd ? 16 : li);
        const int idxC = (vS && sOdd && kO) ? (li - 1) : 17;

        int tgr[16];
        const bool fastL = (L == 16);
        if (fastL) {
            #pragma unroll
            for (int l = 0; l < 16; l++) tgr[l] = tg[l];
        }

        const float* src0 = logits + (size_t)b * T * CC;
        const int nT = (T + 31) >> 5;
        const uint32_t sb0 = s2u(base), sb1 = s2u(base + 1184);

        // ---- issue one tile's cp.async (all lanes; equal commit count) ----
        auto issueTile = [&](int i) {
            const float* g = src0 + (size_t)i * 32 * CC;
            const int nf = min(32, T - (i << 5)) * CC;
            const uint32_t sb = (i & 1) ? sb1 : sb0;
            for (int j = lane; j < (nf >> 2); j += 32)
                cpa16(sb + j * 16, (const float4*)g + j);
            for (int j = (nf & ~3) + lane; j < nf; j += 32)
                cpa4(sb + j * 4, g + j);
            cpcommit();
        };
        issueTile(0);
        if (nT > 1) issueTile(1);

        float al = 0.f, a0 = 0.f, acc2 = 0.f, fin = -1e30f;
        int n = 0;

#define CTC_CAPTURE() do {                                                    \
            float e1 = (endi == 0) ? a0 : __shfl_sync(FULLM, al, endi-1);     \
            float e2 = (endi == 1) ? a0 :                                     \
                       ((endi >= 2) ? __shfl_sync(FULLM, al, endi-2) : 0.f);  \
            fin = lg2f_(e1 + e2) + acc2;                                      \
        } while (0)

        for (int i = 0; i < nT; i++) {
            const int t0 = i << 5;
            const int rows = min(32, T - t0);
            if (i + 1 < nT) asm volatile("cp.async.wait_group 1;" ::: "memory");
            else            asm volatile("cp.async.wait_group 0;" ::: "memory");
            __syncwarp();
            float* bufc = base + ((i & 1) ? 1184 : 0);

            // ---- per-row ex2 (unnormalized) + gather; lane = row ----
            float zrow = 0.f;
            if (lane < rows) {
                float* xr = bufc + lane * 37;          // stride 37: conflict-free
                float s0=0.f,s1=0.f,s2=0.f,s3=0.f;
                #pragma unroll
                for (int c = 0; c < 36; c += 4) {
                    float e0 = ex2f_(xr[c]*LOG2E),   e1 = ex2f_(xr[c+1]*LOG2E);
                    float e2 = ex2f_(xr[c+2]*LOG2E), e3 = ex2f_(xr[c+3]*LOG2E);
                    xr[c]=e0; xr[c+1]=e1; xr[c+2]=e2; xr[c+3]=e3;
                    s0+=e0; s1+=e1; s2+=e2; s3+=e3;
                }
                float e36 = ex2f_(xr[36]*LOG2E); xr[36] = e36;
                float zs = (s0+s1)+(s2+s3)+e36;
                float* pr = P + lane * 19;             // stride 19: conflict-free
                if (fastL) {
                    #pragma unroll
                    for (int l = 0; l < 16; l++) pr[l] = xr[tgr[l]];
                } else {
                    for (int l = 0; l < L; l++) pr[l] = xr[tg[l]];
                }
                pr[16] = e36; pr[17] = 0.f;
                zrow = lg2f_(zs);
                pr[18] = zrow;
            }
            __syncwarp();
            if (i + 2 < nT) issueTile(i + 2);          // buffer just freed

            // ---- recursion over this tile (2 rows per iteration) ----
            const int limit = min(t0 + rows, il);
            const bool fullT = (il >= t0 + rows);
            float tileZ = 0.f;
            if (fullT) {                                // warp-sum of row normalizers
                float v = (lane < rows) ? zrow : 0.f;
                #pragma unroll
                for (int o = 16; o; o >>= 1) v += __shfl_xor_sync(FULLM, v, o);
                tileZ = v;
            }

            if (i == 0) {
                a0 = P[16];
                al = (lane == 0 && vS) ? P[0] : 0.f;
                acc2 = fullT ? -tileZ : -P[18];
                n = 1;
                if (n == il) CTC_CAPTURE();
                if (n < limit) {                        // single step, row 1
                    const float* r1 = P + 19;
                    float A1 = __shfl_up_sync(FULLM, al, 1); if (lane == 0) A1 = a0;
                    float A2 = __shfl_up_sync(FULLM, al, 2);
                    al = (al + A1 + fa*A2) * r1[idxA];
                    a0 *= r1[16];
                    if (!fullT) acc2 -= r1[18];
                    n = 2;
                    if (n == il) CTC_CAPTURE();
                }
            } else if (fullT) {
                acc2 -= tileZ;
            }

            const float* rp = P + (n - t0) * 19;
            #pragma unroll 2
            while (n + 2 <= limit) {
                const float* r1 = rp; const float* r2 = rp + 19;
                float A1 = __shfl_up_sync(FULLM, al, 1); if (lane == 0) A1 = a0;
                float A2 = __shfl_up_sync(FULLM, al, 2);
                A2 = (lane < 2) ? ((lane == 1) ? a0 : 0.f) : A2;
                float A3 = __shfl_up_sync(FULLM, al, 3); if (lane == 2) A3 = a0;
                float A4 = __shfl_up_sync(FULLM, al, 4);   // garbage lanes<4 annihilated
                float Ca = r1[idxA], Cb = r1[idxB], Cc = r1[idxC], P2 = r2[idxA];
                float pbb = r1[16] * r2[16];
                float g1 = (al + A1) + fa*A2;
                float g2 = (A1 + A2) + fb*A3;
                float g3 = (A2 + A3) + fc*A4;
                al = P2 * (Ca*g1 + Cb*g2 + Cc*g3);
                a0 *= pbb;
                if (!fullT) acc2 -= r1[18] + r2[18];
                n += 2; rp += 38;
                if (n == il) CTC_CAPTURE();
                if ((n & 7) == 0) {                     // exact pow2 renorm
                    unsigned Mi = __reduce_max_sync(FULLM,
                        __float_as_uint(fmaxf(al, a0)));
                    int e = (int)(Mi >> 23) - 127;
                    float scale = __uint_as_float((unsigned)(127 - e) << 23);
                    al *= scale; a0 *= scale; acc2 += (float)e;
                }
            }
            if (n < limit) {                            // trailing single (partial il)
                const float* r1 = rp;
                float A1 = __shfl_up_sync(FULLM, al, 1); if (lane == 0) A1 = a0;
                float A2 = __shfl_up_sync(FULLM, al, 2);
                al = (al + A1 + fa*A2) * r1[idxA];
                a0 *= r1[16];
                if (!fullT) acc2 -= r1[18];
                n += 1;
                if (n == il) CTC_CAPTURE();
            }
            __syncwarp();
            if (n >= il) break;
        }
#undef CTC_CAPTURE

        if (lane == 0) {
            const float tlf = (float)(tl > 0 ? tl : 1);
            blkLoss[warp] = -(fin * LN2F) / tlf;
        }
    }

    // ---- per-block partial, then last-block deterministic mean ----
    __syncthreads();
    if (threadIdx.x == 0) {
        float part = blkLoss[0];
        #pragma unroll
        for (int w = 1; w < WPB; w++) part += blkLoss[w];
        g_part[blockIdx.x] = part;
        __threadfence();
        tkt = atomicAdd(&g_ctr, 1u);
    }
    __syncthreads();
    if (tkt == (unsigned)(nBlocks - 1)) {
        __threadfence();
        float s = 0.f;
        for (int i = threadIdx.x; i < nBlocks; i += WPB*32) s += g_part[i];
        __shared__ float sh[WPB*32];
        sh[threadIdx.x] = s;
        __syncthreads();
        if (threadIdx.x < 32) {
            float v = sh[threadIdx.x] + sh[threadIdx.x + 32];
            #pragma unroll
            for (int o = 16; o; o >>= 1) v += __shfl_down_sync(FULLM, v, o);
            if (threadIdx.x == 0) {
                out[0] = v / (float)B;
                g_ctr = 0;                              // graph replays identical
            }
        }
    }
}

extern "C" void kernel_launch(void* const* d_in, const int* in_sizes, int n_in,
                              void* d_out, int out_size)
{
    const float* logits  = (const float*)d_in[0];
    const int*   targets = (const int*)d_in[1];
    const int*   in_len  = (const int*)d_in[2];
    const int*   tgt_len = (const int*)d_in[3];

    const int B = in_sizes[2];
    const int L = in_sizes[1] / B;
    const int T = in_sizes[0] / (B * CC);

    const int blocks = (B + WPB - 1) / WPB;
    const size_t smemBytes = (size_t)WPB * PW * sizeof(float);   // 23.9 KB

    ctc_kernel<<<blocks, WPB*32, smemBytes>>>(
        logits, targets, in_len, tgt_len, (float*)d_out, B, T, L, blocks);
}

// round 16
// speedup vs baseline: 1.4882x; 1.0073x over previous
#include <cuda_runtime.h>
#include <cstdint>

#define FULLM 0xFFFFFFFFu
#define LOG2E 1.4426950408889634f
#define LN2F  0.6931471805599453f
#define CC 37
#define WPB 2
#define PW 3032     // floats/warp: buf0 1184 | buf1 1184 | P 646 (34 rows x 19) | tg 16 | pad 2

// Static device scratch (no allocation allowed)
__device__ float    g_part[4096];
__device__ unsigned g_ctr = 0;

__device__ __forceinline__ float ex2f_(float x){float y;asm("ex2.approx.f32 %0,%1;":"=f"(y):"f"(x));return y;}
__device__ __forceinline__ float lg2f_(float x){float y;asm("lg2.approx.f32 %0,%1;":"=f"(y):"f"(x));return y;}
__device__ __forceinline__ uint32_t s2u(const void* p){return (uint32_t)__cvta_generic_to_shared(p);}
__device__ __forceinline__ void cpa16(uint32_t d,const void* s){asm volatile("cp.async.cg.shared.global [%0],[%1],16;"::"r"(d),"l"(s));}
__device__ __forceinline__ void cpa4 (uint32_t d,const void* s){asm volatile("cp.async.ca.shared.global [%0],[%1],4;"::"r"(d),"l"(s));}
__device__ __forceinline__ void cpcommit(){asm volatile("cp.async.commit_group;" ::: "memory");}

extern __shared__ float smem_dyn[];

// Fused CTC (R12 architecture): one warp per sample, lane k = state k+1,
// state 0 replicated. cp.async double-buffered logits staging; unnormalized
// ex2 probs + log2-normalizer; 2-step-fused linear recursion with the row
// coefficients SOFTWARE-PREFETCHED one iteration ahead (off the alpha chain);
// exact pow2 renorm every 8 rows; ticket-fused deterministic mean.
__global__ void __launch_bounds__(WPB*32)
ctc_kernel(const float* __restrict__ logits, const int* __restrict__ targets,
           const int* __restrict__ in_len, const int* __restrict__ tgt_len,
           float* __restrict__ out, int B, int T, int L, int nBlocks)
{
    const int warp = threadIdx.x >> 5, lane = threadIdx.x & 31;
    const int b = blockIdx.x * WPB + warp;
    float* base = smem_dyn + warp * PW;
    float* P    = base + 2368;               // [34][19]: 0-15 labels,16 blank,17 zero,18 log2Z
    int*   tg   = (int*)(base + 3014);
    __shared__ float    blkLoss[WPB];
    __shared__ unsigned tkt;
    if (lane == 0) blkLoss[warp] = 0.f;

    if (b < B) {
        for (int l = lane; l < L; l += 32) tg[l] = targets[b*L + l];
        __syncwarp();

        const int tl = tgt_len[b], il = in_len[b];
        const int endi = 2 * tl;
        const bool sOdd = !(lane & 1);        // s = lane+1
        const int  li   = lane >> 1;
        const bool vS   = lane < endi;        // s < S = endi+1
        const bool kO  = (li >= 1) && (tg[li]   != tg[li-1]);
        const bool k2O = (li >= 2) && (tg[li-1] != tg[li-2]);
        const float fa = (sOdd && kO)  ? 1.f : 0.f;   // skip into s   (odd only)
        const float fb = (!sOdd && kO) ? 1.f : 0.f;   // skip into s-1 (even only)
        const float fc = (sOdd && k2O) ? 1.f : 0.f;   // skip into s-2 (odd only)
        const int idxA = !vS ? 17 : (sOdd ? li : 16);
        const int idxB = !vS ? 17 : (sOdd ? 16 : li);
        const int idxC = (vS && sOdd && kO) ? (li - 1) : 17;

        int tgr[16];
        const bool fastL = (L == 16);
        if (fastL) {
            #pragma unroll
            for (int l = 0; l < 16; l++) tgr[l] = tg[l];
        }

        const float* src0 = logits + (size_t)b * T * CC;
        const int nT = (T + 31) >> 5;
        const uint32_t sb0 = s2u(base), sb1 = s2u(base + 1184);

        auto issueTile = [&](int i) {
            const float* g = src0 + (size_t)i * 32 * CC;
            const int nf = min(32, T - (i << 5)) * CC;
            const uint32_t sb = (i & 1) ? sb1 : sb0;
            for (int j = lane; j < (nf >> 2); j += 32)
                cpa16(sb + j * 16, (const float4*)g + j);
            for (int j = (nf & ~3) + lane; j < nf; j += 32)
                cpa4(sb + j * 4, g + j);
            cpcommit();
        };
        issueTile(0);
        if (nT > 1) issueTile(1);

        float al = 0.f, a0 = 0.f, acc2 = 0.f, fin = -1e30f;
        int n = 0;

#define CTC_CAPTURE() do {                                                    \
            float e1 = (endi == 0) ? a0 : __shfl_sync(FULLM, al, endi-1);     \
            float e2 = (endi == 1) ? a0 :                                     \
                       ((endi >= 2) ? __shfl_sync(FULLM, al, endi-2) : 0.f);  \
            fin = lg2f_(e1 + e2) + acc2;                                      \
        } while (0)

        for (int i = 0; i < nT; i++) {
            const int t0 = i << 5;
            const int rows = min(32, T - t0);
            if (i + 1 < nT) asm volatile("cp.async.wait_group 1;" ::: "memory");
            else            asm volatile("cp.async.wait_group 0;" ::: "memory");
            __syncwarp();
            float* bufc = base + ((i & 1) ? 1184 : 0);

            // ---- per-row ex2 (unnormalized) + gather; lane = row ----
            float zrow = 0.f;
            if (lane < rows) {
                float* xr = bufc + lane * 37;          // stride 37: conflict-free
                float s0=0.f,s1=0.f,s2=0.f,s3=0.f;
                #pragma unroll
                for (int c = 0; c < 36; c += 4) {
                    float e0 = ex2f_(xr[c]*LOG2E),   e1 = ex2f_(xr[c+1]*LOG2E);
                    float e2 = ex2f_(xr[c+2]*LOG2E), e3 = ex2f_(xr[c+3]*LOG2E);
                    xr[c]=e0; xr[c+1]=e1; xr[c+2]=e2; xr[c+3]=e3;
                    s0+=e0; s1+=e1; s2+=e2; s3+=e3;
                }
                float e36 = ex2f_(xr[36]*LOG2E); xr[36] = e36;
                float zs = (s0+s1)+(s2+s3)+e36;
                float* pr = P + lane * 19;             // stride 19: conflict-free
                if (fastL) {
                    #pragma unroll
                    for (int l = 0; l < 16; l++) pr[l] = xr[tgr[l]];
                } else {
                    for (int l = 0; l < L; l++) pr[l] = xr[tg[l]];
                }
                pr[16] = e36; pr[17] = 0.f;
                zrow = lg2f_(zs);
                pr[18] = zrow;
            }
            __syncwarp();
            if (i + 2 < nT) issueTile(i + 2);          // buffer just freed

            // ---- recursion over this tile (2 rows/iter, coeffs prefetched) ----
            const int limit = min(t0 + rows, il);
            const bool fullT = (il >= t0 + rows);
            float tileZ = 0.f;
            if (fullT) {                                // warp-sum of row normalizers
                float v = (lane < rows) ? zrow : 0.f;
                #pragma unroll
                for (int o = 16; o; o >>= 1) v += __shfl_xor_sync(FULLM, v, o);
                tileZ = v;
            }

            if (i == 0) {
                a0 = P[16];
                al = (lane == 0 && vS) ? P[0] : 0.f;
                acc2 = fullT ? -tileZ : -P[18];
                n = 1;
                if (n == il) CTC_CAPTURE();
                if (n < limit) {                        // single step, row 1
                    const float* r1 = P + 19;
                    float A1 = __shfl_up_sync(FULLM, al, 1); if (lane == 0) A1 = a0;
                    float A2 = __shfl_up_sync(FULLM, al, 2);
                    al = (al + A1 + fa*A2) * r1[idxA];
                    a0 *= r1[16];
                    if (!fullT) acc2 -= r1[18];
                    n = 2;
                    if (n == il) CTC_CAPTURE();
                }
            } else if (fullT) {
                acc2 -= tileZ;
            }

            const float* rp = P + (n - t0) * 19;
            // preload current pair's coefficients (rows <= 33 always in-bounds)
            float Ca = rp[idxA], Cb = rp[idxB], Cc = rp[idxC];
            float P2 = rp[19 + idxA];
            float pbb = rp[16] * rp[35];                // 19+16
            #pragma unroll 2
            while (n + 2 <= limit) {
                const float* rn = rp + 38;
                // prefetch NEXT pair (pad rows 32/33: garbage, never consumed)
                float nCa = rn[idxA], nCb = rn[idxB], nCc = rn[idxC];
                float nP2 = rn[19 + idxA];
                float npbb = rn[16] * rn[35];
                float A1 = __shfl_up_sync(FULLM, al, 1); if (lane == 0) A1 = a0;
                float A2 = __shfl_up_sync(FULLM, al, 2);
                A2 = (lane < 2) ? ((lane == 1) ? a0 : 0.f) : A2;
                float A3 = __shfl_up_sync(FULLM, al, 3); if (lane == 2) A3 = a0;
                float A4 = __shfl_up_sync(FULLM, al, 4); // lanes<4 garbage annihilated
                float g1 = (al + A1) + fa*A2;
                float g2 = (A1 + A2) + fb*A3;
                float g3 = (A2 + A3) + fc*A4;
                al = P2 * (Ca*g1 + Cb*g2 + Cc*g3);
                a0 *= pbb;
                if (!fullT) acc2 -= rp[18] + rp[37];
                n += 2; rp = rn;
                Ca = nCa; Cb = nCb; Cc = nCc; P2 = nP2; pbb = npbb;
                if (n == il) CTC_CAPTURE();
                if ((n & 7) == 0) {                     // exact pow2 renorm
                    unsigned Mi = __reduce_max_sync(FULLM,
                        __float_as_uint(fmaxf(al, a0)));
                    int e = (int)(Mi >> 23) - 127;
                    float scale = __uint_as_float((unsigned)(127 - e) << 23);
                    al *= scale; a0 *= scale; acc2 += (float)e;
                }
            }
            if (n < limit) {                            // trailing single (partial il)
                const float* r1 = rp;
                float A1 = __shfl_up_sync(FULLM, al, 1); if (lane == 0) A1 = a0;
                float A2 = __shfl_up_sync(FULLM, al, 2);
                al = (al + A1 + fa*A2) * r1[idxA];
                a0 *= r1[16];
                if (!fullT) acc2 -= r1[18];
                n += 1;
                if (n == il) CTC_CAPTURE();
            }
            __syncwarp();
            if (n >= il) break;
        }
#undef CTC_CAPTURE

        if (lane == 0) {
            const float tlf = (float)(tl > 0 ? tl : 1);
            blkLoss[warp] = -(fin * LN2F) / tlf;
        }
    }

    // ---- per-block partial, then last-block deterministic mean ----
    __syncthreads();
    if (threadIdx.x == 0) {
        float part = blkLoss[0];
        #pragma unroll
        for (int w = 1; w < WPB; w++) part += blkLoss[w];
        g_part[blockIdx.x] = part;
        __threadfence();
        tkt = atomicAdd(&g_ctr, 1u);
    }
    __syncthreads();
    if (tkt == (unsigned)(nBlocks - 1)) {
        __threadfence();
        float s = 0.f;
        for (int i = threadIdx.x; i < nBlocks; i += WPB*32) s += g_part[i];
        __shared__ float sh[WPB*32];
        sh[threadIdx.x] = s;
        __syncthreads();
        if (threadIdx.x < 32) {
            float v = sh[threadIdx.x] + sh[threadIdx.x + 32];
            #pragma unroll
            for (int o = 16; o; o >>= 1) v += __shfl_down_sync(FULLM, v, o);
            if (threadIdx.x == 0) {
                out[0] = v / (float)B;
                g_ctr = 0;                              // graph replays identical
            }
        }
    }
}

extern "C" void kernel_launch(void* const* d_in, const int* in_sizes, int n_in,
                              void* d_out, int out_size)
{
    const float* logits  = (const float*)d_in[0];
    const int*   targets = (const int*)d_in[1];
    const int*   in_len  = (const int*)d_in[2];
    const int*   tgt_len = (const int*)d_in[3];

    const int B = in_sizes[2];
    const int L = in_sizes[1] / B;
    const int T = in_sizes[0] / (B * CC);

    const int blocks = (B + WPB - 1) / WPB;
    const size_t smemBytes = (size_t)WPB * PW * sizeof(float);   // 24.3 KB

    ctc_kernel<<<blocks, WPB*32, smemBytes>>>(
        logits, targets, in_len, tgt_len, (float*)d_out, B, T, L, blocks);
}